// round 1
// baseline (speedup 1.0000x reference)
#include <cuda_runtime.h>
#include <cuda_bf16.h>
#include <cstdint>

#define B_    8
#define C_    64
#define H_    128
#define W_    128
#define HW_   (H_*W_)
#define COUT_ 64
#define J_    18       // 2*K offset channels per input channel
#define TH    8
#define TW    32

// Scratch: exp(logits) bf16  [B][C][18][H][W]  (302 MB), reciprocal softmax sums [B][H][W]
__device__ __nv_bfloat16 g_exp[(size_t)B_*C_*J_*HW_];
__device__ float g_rsum[(size_t)B_*HW_];

__device__ __forceinline__ unsigned long long pack2(float lo, float hi){
    unsigned long long r;
    asm("mov.b64 %0, {%1, %2};" : "=l"(r) : "f"(lo), "f"(hi));
    return r;
}
__device__ __forceinline__ void unpack2(unsigned long long v, float& lo, float& hi){
    asm("mov.b64 {%0, %1}, %2;" : "=f"(lo), "=f"(hi) : "l"(v));
}
__device__ __forceinline__ unsigned long long fma2(unsigned long long a, unsigned long long b, unsigned long long c){
    unsigned long long d;
    asm("fma.rn.f32x2 %0, %1, %2, %3;" : "=l"(d) : "l"(a), "l"(b), "l"(c));
    return d;
}

// ---------------------------------------------------------------------------
// Kernel 1: grouped 3x3 conv -> 18 logits per (c,pixel) -> exp -> bf16 scratch
//           + per-pixel reciprocal of the 1152-way softmax denominator.
// Block: 256 thr = 32 w-lanes x 8 channel-groups.  Grid: (W/32, H, B)
// ---------------------------------------------------------------------------
__global__ __launch_bounds__(256) void offsets_kernel(
    const float* __restrict__ x, const float* __restrict__ ow, const float* __restrict__ ob)
{
    __shared__ __align__(16) unsigned long long wsh[C_*9*9]; // [c][j2][t] packed j-pairs
    __shared__ __align__(16) unsigned long long bsh[C_*9];   // [c][j2]
    __shared__ float red[8][32];

    int tid = threadIdx.x;
    for (int i = tid; i < C_*81; i += 256){
        int c = i/81, rem = i%81, j2 = rem/9, t = rem%9;
        wsh[i] = pack2(ow[(c*J_ + 2*j2)*9 + t], ow[(c*J_ + 2*j2 + 1)*9 + t]);
    }
    for (int i = tid; i < C_*9; i += 256){
        int c = i/9, j2 = i%9;
        bsh[i] = pack2(ob[c*J_ + 2*j2], ob[c*J_ + 2*j2 + 1]);
    }
    __syncthreads();

    int lane = tid & 31, g = tid >> 5;
    int w = blockIdx.x*32 + lane;
    int h = blockIdx.y;
    int b = blockIdx.z;
    const float* xb = x + (size_t)b*C_*HW_;

    float lsum = 0.f;
    for (int c = g; c < C_; c += 8){
        const float* xc = xb + (size_t)c*HW_;
        unsigned long long x2[9];
        #pragma unroll
        for (int u = 0; u < 3; ++u){
            int hh = h + u - 1;
            bool vy = (unsigned)hh < H_;
            #pragma unroll
            for (int v = 0; v < 3; ++v){
                int ww = w + v - 1;
                float xv = (vy && (unsigned)ww < W_) ? xc[hh*W_ + ww] : 0.f;
                x2[u*3+v] = pack2(xv, xv);
            }
        }
        const unsigned long long* wc = &wsh[c*81];
        __nv_bfloat16* ep = &g_exp[((size_t)b*C_ + c)*J_*HW_ + h*W_ + w];
        #pragma unroll
        for (int j2 = 0; j2 < 9; ++j2){
            unsigned long long acc = bsh[c*9 + j2];
            #pragma unroll
            for (int t = 0; t < 9; ++t) acc = fma2(wc[j2*9 + t], x2[t], acc);
            float l0, l1; unpack2(acc, l0, l1);
            // logits ~ N(0, 0.15): exp without max-subtraction is safe (softmax invariant).
            float e0 = __expf(l0), e1 = __expf(l1);
            lsum += e0 + e1;
            ep[(size_t)(2*j2  )*HW_] = __float2bfloat16(e0);
            ep[(size_t)(2*j2+1)*HW_] = __float2bfloat16(e1);
        }
    }
    red[g][lane] = lsum;
    __syncthreads();
    if (g == 0){
        float s = 0.f;
        #pragma unroll
        for (int gg = 0; gg < 8; ++gg) s += red[gg][lane];
        g_rsum[(size_t)b*HW_ + h*W_ + w] = 1.0f / s;
    }
}

// ---------------------------------------------------------------------------
// Kernel 2: fused bilinear deformable sampling + [px x 576]x[576 x 64] GEMM.
// Since dy,dx in (0,1), the 4 bilinear corners are the static 4x4 stencil
// rows h-1..h+2 / cols w-1..w+2 -> stage x tile (+halo) in smem, zero-padded.
// Block: 256 thr = one 8x32 pixel tile, thread-per-pixel, acc = 32 f32x2.
// ---------------------------------------------------------------------------
__global__ __launch_bounds__(256, 2) void deform_kernel(
    const float* __restrict__ x, const float* __restrict__ dw, const float* __restrict__ db,
    float* __restrict__ out)
{
    __shared__ float xsh[TH+3][TW+4];            // 11 x 36 (35 used cols)
    __shared__ __align__(16) float Wsh[9*64];    // [k][o], o-pairs read as 64-bit

    int tid = threadIdx.x;
    int lx = tid & 31, ly = tid >> 5;
    int w0 = blockIdx.x*TW, h0 = blockIdx.y*TH, b = blockIdx.z;
    int h = h0 + ly, w = w0 + lx;
    float r = g_rsum[(size_t)b*HW_ + h*W_ + w];

    unsigned long long acc[32];
    #pragma unroll
    for (int o2 = 0; o2 < 32; ++o2) acc[o2] = pack2(db[2*o2], db[2*o2+1]);

    const float* xb = x + (size_t)b*C_*HW_;

    for (int c = 0; c < C_; ++c){
        __syncthreads();
        const float* xc = xb + (size_t)c*HW_;
        for (int i = tid; i < 11*35; i += 256){
            int rr = i/35, cc = i%35;
            int gh = h0 - 1 + rr, gw = w0 - 1 + cc;
            xsh[rr][cc] = ((unsigned)gh < H_ && (unsigned)gw < W_) ? xc[gh*W_ + gw] : 0.f;
        }
        for (int i = tid; i < 576; i += 256){
            int k = i >> 6, o = i & 63;
            Wsh[i] = dw[((size_t)o*C_ + c)*9 + k];
        }
        __syncthreads();

        const __nv_bfloat16* ep = &g_exp[((size_t)b*C_ + c)*J_*HW_ + h*W_ + w];
        unsigned long long s2[9];
        #pragma unroll
        for (int k = 0; k < 9; ++k){
            float dy = __bfloat162float(ep[(size_t)(2*k  )*HW_]) * r;
            float dx = __bfloat162float(ep[(size_t)(2*k+1)*HW_]) * r;
            int ky = k/3, kx = k%3;
            float A  = xsh[ly+ky  ][lx+kx  ];
            float Bv = xsh[ly+ky  ][lx+kx+1];
            float Cv = xsh[ly+ky+1][lx+kx  ];
            float Dv = xsh[ly+ky+1][lx+kx+1];
            float top = A  + dx*(Bv - A);
            float bot = Cv + dx*(Dv - Cv);
            float s   = top + dy*(bot - top);
            s2[k] = pack2(s, s);
        }
        #pragma unroll
        for (int k = 0; k < 9; ++k){
            const unsigned long long* wr = (const unsigned long long*)&Wsh[k*64];
            #pragma unroll
            for (int o2 = 0; o2 < 32; ++o2)
                acc[o2] = fma2(wr[o2], s2[k], acc[o2]);
        }
    }

    float* op = out + (size_t)b*COUT_*HW_ + h*W_ + w;
    #pragma unroll
    for (int o2 = 0; o2 < 32; ++o2){
        float lo, hi; unpack2(acc[o2], lo, hi);
        op[(size_t)(2*o2  )*HW_] = lo;
        op[(size_t)(2*o2+1)*HW_] = hi;
    }
}

extern "C" void kernel_launch(void* const* d_in, const int* in_sizes, int n_in,
                              void* d_out, int out_size)
{
    const float* x  = (const float*)d_in[0];
    const float* ow = (const float*)d_in[1];
    const float* ob = (const float*)d_in[2];
    const float* dw = (const float*)d_in[3];
    const float* db = (const float*)d_in[4];
    float* out = (float*)d_out;

    dim3 g1(W_/32, H_, B_);
    offsets_kernel<<<g1, 256>>>(x, ow, ob);

    dim3 g2(W_/TW, H_/TH, B_);
    deform_kernel<<<g2, 256>>>(x, dw, db, out);
}

// round 3
// speedup vs baseline: 1.1147x; 1.1147x over previous
#include <cuda_runtime.h>
#include <cuda_bf16.h>
#include <cstdint>

#define B_    8
#define C_    64
#define H_    128
#define W_    128
#define HW_   (H_*W_)
#define COUT_ 64
#define J_    18
#define TH    8
#define TW    32

// Scratch: exp(logits) as bf16x2 pairs (e_dy,e_dx)  [B][C][9][H][W]  (302 MB)
__device__ __nv_bfloat162 g_exp[(size_t)B_*C_*9*HW_];
__device__ float g_rsum[(size_t)B_*HW_];

typedef unsigned long long ull;

__device__ __forceinline__ ull pack2(float lo, float hi){
    ull r; asm("mov.b64 %0, {%1, %2};" : "=l"(r) : "f"(lo), "f"(hi)); return r;
}
__device__ __forceinline__ void unpack2(ull v, float& lo, float& hi){
    asm("mov.b64 {%0, %1}, %2;" : "=f"(lo), "=f"(hi) : "l"(v));
}
__device__ __forceinline__ ull fma2(ull a, ull b, ull c){
    ull d; asm("fma.rn.f32x2 %0, %1, %2, %3;" : "=l"(d) : "l"(a), "l"(b), "l"(c)); return d;
}

// ---------------------------------------------------------------------------
// Kernel 1: grouped 3x3 conv -> 18 logits per (c,pixel) -> exp -> bf16x2 scratch
//           + per-pixel reciprocal of the 1152-way softmax denominator.
// ---------------------------------------------------------------------------
__global__ __launch_bounds__(256) void offsets_kernel(
    const float* __restrict__ x, const float* __restrict__ ow, const float* __restrict__ ob)
{
    __shared__ __align__(16) ull wsh[C_*9*9]; // [c][j2][t] packed (dy,dx)-pairs
    __shared__ __align__(16) ull bsh[C_*9];
    __shared__ float red[8][32];

    int tid = threadIdx.x;
    for (int i = tid; i < C_*81; i += 256){
        int c = i/81, rem = i%81, j2 = rem/9, t = rem%9;
        wsh[i] = pack2(ow[(c*J_ + 2*j2)*9 + t], ow[(c*J_ + 2*j2 + 1)*9 + t]);
    }
    for (int i = tid; i < C_*9; i += 256){
        int c = i/9, j2 = i%9;
        bsh[i] = pack2(ob[c*J_ + 2*j2], ob[c*J_ + 2*j2 + 1]);
    }
    __syncthreads();

    int lane = tid & 31, g = tid >> 5;
    int w = blockIdx.x*32 + lane;
    int h = blockIdx.y;
    int b = blockIdx.z;
    const float* xb = x + (size_t)b*C_*HW_;

    float lsum = 0.f;
    for (int c = g; c < C_; c += 8){
        const float* xc = xb + (size_t)c*HW_;
        ull x2[9];
        #pragma unroll
        for (int u = 0; u < 3; ++u){
            int hh = h + u - 1;
            bool vy = (unsigned)hh < H_;
            #pragma unroll
            for (int v = 0; v < 3; ++v){
                int ww = w + v - 1;
                float xv = (vy && (unsigned)ww < W_) ? xc[hh*W_ + ww] : 0.f;
                x2[u*3+v] = pack2(xv, xv);
            }
        }
        const ull* wc = &wsh[c*81];
        __nv_bfloat162* ep = &g_exp[((size_t)b*C_ + c)*9*HW_ + h*W_ + w];
        #pragma unroll
        for (int j2 = 0; j2 < 9; ++j2){
            ull acc = bsh[c*9 + j2];
            #pragma unroll
            for (int t = 0; t < 9; ++t) acc = fma2(wc[j2*9 + t], x2[t], acc);
            float l0, l1; unpack2(acc, l0, l1);
            float e0 = __expf(l0), e1 = __expf(l1);   // logits ~N(0,0.15): safe w/o max-sub
            lsum += e0 + e1;
            __nv_bfloat162 v; v.x = __float2bfloat16(e0); v.y = __float2bfloat16(e1);
            ep[(size_t)j2*HW_] = v;
        }
    }
    red[g][lane] = lsum;
    __syncthreads();
    if (g == 0){
        float s = 0.f;
        #pragma unroll
        for (int gg = 0; gg < 8; ++gg) s += red[gg][lane];
        g_rsum[(size_t)b*HW_ + h*W_ + w] = 1.0f / s;
    }
}

// ---------------------------------------------------------------------------
// Kernel 2: fused bilinear sampling + register-tiled GEMM.
// Block = 8x32 pixel tile (M=256) x all 64 outputs (N=64), K=64c*9k.
// Thread tile: 4 pixels x 16 outputs (8 f32x2 pairs) -> 32 FFMA2 per k-step
// fed by 1 LDS.128 (samples) + 8 broadcast LDS.64 (W pairs).
// ---------------------------------------------------------------------------
__global__ __launch_bounds__(256, 2) void deform_kernel(
    const float* __restrict__ x, const float* __restrict__ dw, const float* __restrict__ db,
    float* __restrict__ out)
{
    __shared__ float xsh[TH+3][TW+4];               // 11 x 36 (35 used)
    __shared__ __align__(16) float Wsh[9][64];      // [k][o]
    __shared__ __align__(16) float ssh[9][256];     // [k][pixel]

    int tid = threadIdx.x;
    int lx = tid & 31, ly = tid >> 5;               // sampling: thread <-> pixel tid
    int w0 = blockIdx.x*TW, h0 = blockIdx.y*TH, b = blockIdx.z;
    float r = g_rsum[(size_t)b*HW_ + (h0+ly)*W_ + (w0+lx)];

    int tidm = tid & 63;                            // pixel group: 4*tidm..+3
    int tidn = tid >> 6;                            // output group: 16*tidn..+15

    ull acc[4][8];
    #pragma unroll
    for (int j = 0; j < 8; ++j){
        ull bi = pack2(db[16*tidn + 2*j], db[16*tidn + 2*j + 1]);
        #pragma unroll
        for (int m = 0; m < 4; ++m) acc[m][j] = bi;
    }

    const float* xb = x + (size_t)b*C_*HW_;

    for (int c = 0; c < C_; ++c){
        __syncthreads();
        // stage x halo + W slice
        const float* xc = xb + (size_t)c*HW_;
        for (int i = tid; i < 11*35; i += 256){
            int rr = i/35, cc = i%35;
            int gh = h0 - 1 + rr, gw = w0 - 1 + cc;
            xsh[rr][cc] = ((unsigned)gh < H_ && (unsigned)gw < W_) ? xc[gh*W_ + gw] : 0.f;
        }
        for (int i = tid; i < 576; i += 256){
            int o = i/9, k = i%9;
            Wsh[k][o] = dw[((size_t)o*C_ + c)*9 + k];
        }
        __syncthreads();

        // bilinear sampling: dy,dx in (0,1) => static 4x4 stencil
        const __nv_bfloat162* ep = &g_exp[((size_t)b*C_ + c)*9*HW_ + (h0+ly)*W_ + (w0+lx)];
        #pragma unroll
        for (int k = 0; k < 9; ++k){
            __nv_bfloat162 pe = ep[(size_t)k*HW_];
            float dy = __bfloat162float(pe.x) * r;
            float dx = __bfloat162float(pe.y) * r;
            int ky = k/3, kx = k%3;
            float A  = xsh[ly+ky  ][lx+kx  ];
            float Bv = xsh[ly+ky  ][lx+kx+1];
            float Cv = xsh[ly+ky+1][lx+kx  ];
            float Dv = xsh[ly+ky+1][lx+kx+1];
            float top = A  + dx*(Bv - A);
            float bot = Cv + dx*(Dv - Cv);
            ssh[k][tid] = top + dy*(bot - top);
        }
        __syncthreads();

        // register-tiled GEMM over this channel's 9 k-steps
        #pragma unroll
        for (int k = 0; k < 9; ++k){
            float4 s4 = *(const float4*)&ssh[k][4*tidm];
            const ull* wr = (const ull*)&Wsh[k][16*tidn];
            ull w2[8];
            #pragma unroll
            for (int j = 0; j < 8; ++j) w2[j] = wr[j];
            ull sm[4];
            sm[0] = pack2(s4.x, s4.x); sm[1] = pack2(s4.y, s4.y);
            sm[2] = pack2(s4.z, s4.z); sm[3] = pack2(s4.w, s4.w);
            #pragma unroll
            for (int m = 0; m < 4; ++m)
                #pragma unroll
                for (int j = 0; j < 8; ++j)
                    acc[m][j] = fma2(w2[j], sm[m], acc[m][j]);
        }
    }

    // store: 4 consecutive w per pixel group -> STG.128 per output channel
    int hh = h0 + (tidm >> 3);
    int ww = w0 + (tidm & 7)*4;
    float* op = out + ((size_t)b*COUT_ + 16*tidn)*HW_ + hh*W_ + ww;
    #pragma unroll
    for (int j = 0; j < 8; ++j){
        float lo[4], hi[4];
        #pragma unroll
        for (int m = 0; m < 4; ++m) unpack2(acc[m][j], lo[m], hi[m]);
        float4 vlo = {lo[0], lo[1], lo[2], lo[3]};
        float4 vhi = {hi[0], hi[1], hi[2], hi[3]};
        *(float4*)&op[(size_t)(2*j  )*HW_] = vlo;
        *(float4*)&op[(size_t)(2*j+1)*HW_] = vhi;
    }
}

extern "C" void kernel_launch(void* const* d_in, const int* in_sizes, int n_in,
                              void* d_out, int out_size)
{
    const float* x  = (const float*)d_in[0];
    const float* ow = (const float*)d_in[1];
    const float* ob = (const float*)d_in[2];
    const float* dw = (const float*)d_in[3];
    const float* db = (const float*)d_in[4];
    float* out = (float*)d_out;

    dim3 g1(W_/32, H_, B_);
    offsets_kernel<<<g1, 256>>>(x, ow, ob);

    dim3 g2(W_/TW, H_/TH, B_);
    deform_kernel<<<g2, 256>>>(x, dw, db, out);
}

// round 4
// speedup vs baseline: 1.6640x; 1.4928x over previous
#include <cuda_runtime.h>
#include <cuda_bf16.h>
#include <cstdint>

#define B_    8
#define C_    64
#define H_    128
#define W_    128
#define HW_   (H_*W_)
#define COUT_ 64
#define J_    18
#define TH    8
#define TW    32

// Scratch: exp(logits) as bf16x2 pairs (e_dy,e_dx)  [B][C][9][H][W]  (302 MB)
__device__ __nv_bfloat162 g_exp[(size_t)B_*C_*9*HW_];
__device__ float g_rsum[(size_t)B_*HW_];
__device__ float g_wt[(size_t)C_*9*COUT_];   // deform_w transposed to [c][k][o]

typedef unsigned long long ull;

__device__ __forceinline__ ull pack2(float lo, float hi){
    ull r; asm("mov.b64 %0, {%1, %2};" : "=l"(r) : "f"(lo), "f"(hi)); return r;
}
__device__ __forceinline__ void unpack2(ull v, float& lo, float& hi){
    asm("mov.b64 {%0, %1}, %2;" : "=f"(lo), "=f"(hi) : "l"(v));
}
__device__ __forceinline__ ull fma2(ull a, ull b, ull c){
    ull d; asm("fma.rn.f32x2 %0, %1, %2, %3;" : "=l"(d) : "l"(a), "l"(b), "l"(c)); return d;
}
__device__ __forceinline__ uint32_t s2u(const void* p){
    uint32_t a;
    asm("{ .reg .u64 t; cvta.to.shared.u64 t, %1; cvt.u32.u64 %0, t; }" : "=r"(a) : "l"(p));
    return a;
}
__device__ __forceinline__ void cp4(uint32_t dst, const void* src, bool pred){
    asm volatile("cp.async.ca.shared.global [%0], [%1], 4, %2;"
                 :: "r"(dst), "l"(src), "r"(pred ? 4u : 0u));
}
__device__ __forceinline__ void cp16(uint32_t dst, const void* src){
    asm volatile("cp.async.cg.shared.global [%0], [%1], 16;" :: "r"(dst), "l"(src));
}
#define CP_COMMIT() asm volatile("cp.async.commit_group;" ::: "memory")
#define CP_WAIT0()  asm volatile("cp.async.wait_group 0;"  ::: "memory")

// ---------------------------------------------------------------------------
// Kernel 0: transpose deform_w [o][c][k] -> g_wt [c][k][o]
// ---------------------------------------------------------------------------
__global__ void wtrans_kernel(const float* __restrict__ dw){
    int i = blockIdx.x*256 + threadIdx.x;
    if (i < C_*9*COUT_){
        int o = i % COUT_, k = (i/COUT_) % 9, c = i/(9*COUT_);
        g_wt[i] = dw[((size_t)o*C_ + c)*9 + k];
    }
}

// ---------------------------------------------------------------------------
// Kernel 1: grouped 3x3 conv -> 18 logits per (c,pixel) -> exp -> bf16x2 scratch
//           + per-pixel reciprocal of the 1152-way softmax denominator.
// ---------------------------------------------------------------------------
__global__ __launch_bounds__(256) void offsets_kernel(
    const float* __restrict__ x, const float* __restrict__ ow, const float* __restrict__ ob)
{
    __shared__ __align__(16) ull wsh[C_*9*9]; // [c][j2][t] packed (dy,dx)-pairs
    __shared__ __align__(16) ull bsh[C_*9];
    __shared__ float red[8][32];

    int tid = threadIdx.x;
    for (int i = tid; i < C_*81; i += 256){
        int c = i/81, rem = i%81, j2 = rem/9, t = rem%9;
        wsh[i] = pack2(ow[(c*J_ + 2*j2)*9 + t], ow[(c*J_ + 2*j2 + 1)*9 + t]);
    }
    for (int i = tid; i < C_*9; i += 256){
        int c = i/9, j2 = i%9;
        bsh[i] = pack2(ob[c*J_ + 2*j2], ob[c*J_ + 2*j2 + 1]);
    }
    __syncthreads();

    int lane = tid & 31, g = tid >> 5;
    int w = blockIdx.x*32 + lane;
    int h = blockIdx.y;
    int b = blockIdx.z;
    const float* xb = x + (size_t)b*C_*HW_;

    float lsum = 0.f;
    for (int c = g; c < C_; c += 8){
        const float* xc = xb + (size_t)c*HW_;
        ull x2[9];
        #pragma unroll
        for (int u = 0; u < 3; ++u){
            int hh = h + u - 1;
            bool vy = (unsigned)hh < H_;
            #pragma unroll
            for (int v = 0; v < 3; ++v){
                int ww = w + v - 1;
                float xv = (vy && (unsigned)ww < W_) ? xc[hh*W_ + ww] : 0.f;
                x2[u*3+v] = pack2(xv, xv);
            }
        }
        const ull* wc = &wsh[c*81];
        __nv_bfloat162* ep = &g_exp[((size_t)b*C_ + c)*9*HW_ + h*W_ + w];
        #pragma unroll
        for (int j2 = 0; j2 < 9; ++j2){
            ull acc = bsh[c*9 + j2];
            #pragma unroll
            for (int t = 0; t < 9; ++t) acc = fma2(wc[j2*9 + t], x2[t], acc);
            float l0, l1; unpack2(acc, l0, l1);
            float e0 = __expf(l0), e1 = __expf(l1);   // logits ~N(0,0.15): safe w/o max-sub
            lsum += e0 + e1;
            __nv_bfloat162 v; v.x = __float2bfloat16(e0); v.y = __float2bfloat16(e1);
            ep[(size_t)j2*HW_] = v;
        }
    }
    red[g][lane] = lsum;
    __syncthreads();
    if (g == 0){
        float s = 0.f;
        #pragma unroll
        for (int gg = 0; gg < 8; ++gg) s += red[gg][lane];
        g_rsum[(size_t)b*HW_ + h*W_ + w] = 1.0f / s;
    }
}

// ---------------------------------------------------------------------------
// Kernel 2: fused bilinear sampling + register-tiled GEMM, software-pipelined:
//   cp.async double-buffered x-halo + W staging (issued under previous GEMM),
//   ep (offset exp) prefetched one channel ahead into registers.
// Block = 8x32 pixel tile (M=256) x 64 outputs; thread tile 4px x 16out.
// ---------------------------------------------------------------------------
__global__ __launch_bounds__(256, 2) void deform_kernel(
    const float* __restrict__ x, const float* __restrict__ db,
    float* __restrict__ out)
{
    __shared__ float xsh[2][11][36];
    __shared__ __align__(16) float Wsh[2][9][64];
    __shared__ __align__(16) float ssh[9][256];

    int tid = threadIdx.x;
    int lx = tid & 31, ly = tid >> 5;               // sampling: thread <-> pixel
    int w0 = blockIdx.x*TW, h0 = blockIdx.y*TH, b = blockIdx.z;
    float r = g_rsum[(size_t)b*HW_ + (h0+ly)*W_ + (w0+lx)];

    int tidm = tid & 63;                            // pixel group: 4*tidm..+3
    int tidn = tid >> 6;                            // output group: 16*tidn..+15

    ull acc[4][8];
    #pragma unroll
    for (int j = 0; j < 8; ++j){
        ull bi = pack2(db[16*tidn + 2*j], db[16*tidn + 2*j + 1]);
        #pragma unroll
        for (int m = 0; m < 4; ++m) acc[m][j] = bi;
    }

    const float* xb = x + (size_t)b*C_*HW_;
    const __nv_bfloat162* epbase = g_exp + ((size_t)b*C_)*9*HW_ + (h0+ly)*W_ + (w0+lx);

    // staging helper (cp.async)
    auto stage = [&](int c, int p){
        const float* xc = xb + (size_t)c*HW_;
        uint32_t xdst = s2u(&xsh[p][0][0]);
        for (int i = tid; i < 11*35; i += 256){
            int rr = i/35, cc = i%35;
            int gh = h0 - 1 + rr, gw = w0 - 1 + cc;
            bool v = ((unsigned)gh < H_) && ((unsigned)gw < W_);
            int ghc = min(max(gh,0),H_-1), gwc = min(max(gw,0),W_-1);
            cp4(xdst + (uint32_t)(rr*36 + cc)*4u, xc + ghc*W_ + gwc, v);
        }
        if (tid < 144)
            cp16(s2u(&Wsh[p][0][0]) + (uint32_t)tid*16u, g_wt + (size_t)c*576 + tid*4);
    };

    // prologue: stage c=0, prefetch ep for c=0
    stage(0, 0);
    CP_COMMIT();
    uint32_t epr[9];
    {
        const uint32_t* e0 = (const uint32_t*)epbase;
        #pragma unroll
        for (int k = 0; k < 9; ++k) epr[k] = __ldg(&e0[(size_t)k*HW_]);
    }

    int p = 0;
    for (int c = 0; c < C_; ++c){
        CP_WAIT0();
        __syncthreads();                 // xsh[p]/Wsh[p] ready; prev GEMM done with ssh

        // bilinear sampling: dy,dx in (0,1) => static 4x4 stencil
        #pragma unroll
        for (int k = 0; k < 9; ++k){
            __nv_bfloat162 pe = *(const __nv_bfloat162*)&epr[k];
            float dy = __bfloat162float(pe.x) * r;
            float dx = __bfloat162float(pe.y) * r;
            int ky = k/3, kx = k%3;
            float A  = xsh[p][ly+ky  ][lx+kx  ];
            float Bv = xsh[p][ly+ky  ][lx+kx+1];
            float Cv = xsh[p][ly+ky+1][lx+kx  ];
            float Dv = xsh[p][ly+ky+1][lx+kx+1];
            float top = A  + dx*(Bv - A);
            float bot = Cv + dx*(Dv - Cv);
            ssh[k][tid] = top + dy*(bot - top);
        }
        // prefetch ep for next channel (latency hidden under GEMM below)
        if (c + 1 < C_){
            const uint32_t* en = (const uint32_t*)(epbase + (size_t)(c+1)*9*HW_);
            #pragma unroll
            for (int k = 0; k < 9; ++k) epr[k] = __ldg(&en[(size_t)k*HW_]);
        }
        __syncthreads();                 // ssh ready

        // stage next channel's x/W under this GEMM
        if (c + 1 < C_){
            stage(c + 1, p ^ 1);
            CP_COMMIT();
        }

        // register-tiled GEMM over this channel's 9 k-steps
        #pragma unroll
        for (int k = 0; k < 9; ++k){
            float4 s4 = *(const float4*)&ssh[k][4*tidm];
            const ull* wr = (const ull*)&Wsh[p][k][16*tidn];
            ull w2[8];
            #pragma unroll
            for (int j = 0; j < 8; ++j) w2[j] = wr[j];
            ull sm[4];
            sm[0] = pack2(s4.x, s4.x); sm[1] = pack2(s4.y, s4.y);
            sm[2] = pack2(s4.z, s4.z); sm[3] = pack2(s4.w, s4.w);
            #pragma unroll
            for (int m = 0; m < 4; ++m)
                #pragma unroll
                for (int j = 0; j < 8; ++j)
                    acc[m][j] = fma2(w2[j], sm[m], acc[m][j]);
        }
        p ^= 1;
    }

    // store: 4 consecutive w per pixel group -> STG.128 per output channel
    int hh = h0 + (tidm >> 3);
    int ww = w0 + (tidm & 7)*4;
    float* op = out + ((size_t)b*COUT_ + 16*tidn)*HW_ + hh*W_ + ww;
    #pragma unroll
    for (int j = 0; j < 8; ++j){
        float lo[4], hi[4];
        #pragma unroll
        for (int m = 0; m < 4; ++m) unpack2(acc[m][j], lo[m], hi[m]);
        float4 vlo = {lo[0], lo[1], lo[2], lo[3]};
        float4 vhi = {hi[0], hi[1], hi[2], hi[3]};
        *(float4*)&op[(size_t)(2*j  )*HW_] = vlo;
        *(float4*)&op[(size_t)(2*j+1)*HW_] = vhi;
    }
}

extern "C" void kernel_launch(void* const* d_in, const int* in_sizes, int n_in,
                              void* d_out, int out_size)
{
    const float* x  = (const float*)d_in[0];
    const float* ow = (const float*)d_in[1];
    const float* ob = (const float*)d_in[2];
    const float* dw = (const float*)d_in[3];
    const float* db = (const float*)d_in[4];
    float* out = (float*)d_out;

    wtrans_kernel<<<(C_*9*COUT_ + 255)/256, 256>>>(dw);

    dim3 g1(W_/32, H_, B_);
    offsets_kernel<<<g1, 256>>>(x, ow, ob);

    dim3 g2(W_/TW, H_/TH, B_);
    deform_kernel<<<g2, 256>>>(x, db, out);
}